// round 4
// baseline (speedup 1.0000x reference)
#include <cuda_runtime.h>
#include <math_constants.h>

// Problem constants
#define B_    32
#define L_    1000
#define NCHAR 256
#define DM    512
#define NH    8
#define DH    64
#define XROWS (NCHAR + L_)   // 1256
#define XPAD  1280           // padded row count (multiple of 64), pad rows zero
#define LN10000 9.210340371976184f

// Scratch (device globals: no allocation allowed)
__device__ float g_X  [XPAD * DM];        // [emb(256) ; pe(1000) ; zeros(24)]
__device__ float g_q  [B_ * DM];          // per-batch query (single position)
__device__ float g_u  [NH * B_ * DM];     // U[i=h*32+b][e] = q[b,h] @ Wk_head
__device__ float g_dot[NH * B_ * XPAD];   // D[i][r] = (U[i] . X[r]) * scale
__device__ float g_wr [NH * B_ * XPAD];   // WR[i][r] softmax weight rows
__device__ float g_y  [NH * B_ * DM];     // Y[i][e] = WR[i] @ X

// ---------------------------------------------------------------------------
// Kernel 1: build X = [emb(256,512) ; pe(1000,512) ; zeros]
// ---------------------------------------------------------------------------
__global__ void build_x_kernel(const float* __restrict__ emb) {
    int i = blockIdx.x * blockDim.x + threadIdx.x;
    if (i >= XPAD * DM) return;
    int r = i >> 9;       // /512
    int e = i & 511;
    float v = 0.f;
    if (r < NCHAR) {
        v = emb[i];
    } else if (r < XROWS) {
        int t = r - NCHAR;
        int pair = e >> 1;
        float div = expf((float)(2 * pair) * (-LN10000 / (float)DM));
        float ang = (float)t * div;
        v = (e & 1) ? cosf(ang) : sinf(ang);
    }
    g_X[i] = v;
}

// ---------------------------------------------------------------------------
// Kernel 2: q[b] = Wq @ (emb[c_p] + pe_p) + bq
// ---------------------------------------------------------------------------
__global__ void q_kernel(const int* __restrict__ data,
                         const int* __restrict__ lengths,
                         const float* __restrict__ emb,
                         const float* __restrict__ Wq,
                         const float* __restrict__ bq) {
    int b = blockIdx.x;
    __shared__ float xs[DM];
    int p = lengths[b] - 1;
    if (p < 0) p = 0;
    if (p >= L_) p = L_ - 1;
    int c = data[(size_t)b * L_ + p] & (NCHAR - 1);
    int tid = threadIdx.x;           // 512
    {
        int e = tid;
        int pair = e >> 1;
        float div = expf((float)(2 * pair) * (-LN10000 / (float)DM));
        float ang = (float)p * div;
        float pe = (e & 1) ? cosf(ang) : sinf(ang);
        xs[e] = emb[(size_t)c * DM + e] + pe;
    }
    __syncthreads();
    int w = tid >> 5, lane = tid & 31;
    for (int j = w * 32; j < w * 32 + 32; j++) {
        const float* wr = Wq + (size_t)j * DM;
        float s = 0.f;
        #pragma unroll 4
        for (int e = lane; e < DM; e += 32) s += wr[e] * xs[e];
        #pragma unroll
        for (int off = 16; off; off >>= 1) s += __shfl_xor_sync(0xffffffffu, s, off);
        if (lane == 0) g_q[b * DM + j] = s + bq[j];
    }
}

// ---------------------------------------------------------------------------
// Kernel 3: U[h*32+b][e] = sum_d q[b, h*64+d] * Wk[h*64+d][e]
// grid (NH, B_), 256 threads; thread owns 2 consecutive e.
// ---------------------------------------------------------------------------
__global__ void u_kernel(const float* __restrict__ Wk) {
    int h = blockIdx.x, b = blockIdx.y;
    __shared__ float qs[DH];
    int tid = threadIdx.x;           // 256
    if (tid < DH) qs[tid] = g_q[b * DM + h * DH + tid];
    __syncthreads();
    int e0 = tid * 2;
    float a0 = 0.f, a1 = 0.f;
    const float* Wbase = Wk + (size_t)(h * DH) * DM;
    #pragma unroll 8
    for (int d = 0; d < DH; d++) {
        float qd = qs[d];
        float2 wv = *(const float2*)(Wbase + (size_t)d * DM + e0);
        a0 += qd * wv.x;
        a1 += qd * wv.y;
    }
    *(float2*)(g_u + (size_t)(h * B_ + b) * DM + e0) = make_float2(a0, a1);
}

// ---------------------------------------------------------------------------
// Kernel 4: D = U @ X^T (NT GEMM, scaled by 1/sqrt(DH)).
// M=256 (i), N=1280 (r), K=512. Tiles 64x64, BK=16, 4x4 blocking.
// ---------------------------------------------------------------------------
#define BM 64
#define BN 64
#define BK 16
__global__ void d_gemm_kernel() {
    int m0 = blockIdx.y * BM;
    int n0 = blockIdx.x * BN;

    __shared__ float As[BK][BM + 4];
    __shared__ float Bs[BK][BN + 4];

    int tid  = threadIdx.x;          // 256
    int lrow = tid >> 2;             // 0..63
    int lcol = (tid & 3) * 4;        // 0,4,8,12
    int ty = tid >> 4;               // 0..15
    int tx = tid & 15;               // 0..15

    float acc[4][4] = {};

    for (int k0 = 0; k0 < DM; k0 += BK) {
        float4 av = *(const float4*)(g_u + (size_t)(m0 + lrow) * DM + k0 + lcol);
        As[lcol + 0][lrow] = av.x; As[lcol + 1][lrow] = av.y;
        As[lcol + 2][lrow] = av.z; As[lcol + 3][lrow] = av.w;

        float4 bv4 = *(const float4*)(g_X + (size_t)(n0 + lrow) * DM + k0 + lcol);
        Bs[lcol + 0][lrow] = bv4.x; Bs[lcol + 1][lrow] = bv4.y;
        Bs[lcol + 2][lrow] = bv4.z; Bs[lcol + 3][lrow] = bv4.w;

        __syncthreads();

        #pragma unroll
        for (int kk = 0; kk < BK; kk++) {
            float4 a4 = *(const float4*)&As[kk][ty * 4];
            float4 b4 = *(const float4*)&Bs[kk][tx * 4];
            float a[4] = {a4.x, a4.y, a4.z, a4.w};
            float b[4] = {b4.x, b4.y, b4.z, b4.w};
            #pragma unroll
            for (int i = 0; i < 4; i++)
                #pragma unroll
                for (int j = 0; j < 4; j++)
                    acc[i][j] += a[i] * b[j];
        }
        __syncthreads();
    }

    #pragma unroll
    for (int i = 0; i < 4; i++) {
        int r = m0 + ty * 4 + i;
        #pragma unroll
        for (int j = 0; j < 4; j++) {
            int c = n0 + tx * 4 + j;
            g_dot[(size_t)r * XPAD + c] = acc[i][j] * 0.125f;  // 1/sqrt(64)
        }
    }
}

// ---------------------------------------------------------------------------
// Kernel 5: per (h,b) softmax over valid positions + char binning.
// WR[i][c]      = sum of weights of positions with char c   (c < 256)
// WR[i][256+t]  = weight of position t (0 if t >= count); tail zeros.
// ---------------------------------------------------------------------------
__global__ void softmax_bin_kernel(const int* __restrict__ data,
                                   const int* __restrict__ lengths) {
    int h = blockIdx.x;
    int b = blockIdx.y;
    int i = h * B_ + b;
    __shared__ float s[L_];
    __shared__ float bins[NCHAR];
    __shared__ float red[8];

    int tid = threadIdx.x;       // 256
    int count = lengths[b];
    if (count < 1) count = 1;
    if (count > L_) count = L_;

    const float* D = g_dot + (size_t)i * XPAD;

    float lm = -CUDART_INF_F;
    for (int t = tid; t < count; t += 256) {
        int c = data[(size_t)b * L_ + t] & (NCHAR - 1);
        float v = D[NCHAR + t] + D[c];        // already scaled
        s[t] = v;
        lm = fmaxf(lm, v);
    }
    #pragma unroll
    for (int off = 16; off; off >>= 1) lm = fmaxf(lm, __shfl_xor_sync(0xffffffffu, lm, off));
    if ((tid & 31) == 0) red[tid >> 5] = lm;
    __syncthreads();
    float M = -CUDART_INF_F;
    #pragma unroll
    for (int k = 0; k < 8; k++) M = fmaxf(M, red[k]);
    __syncthreads();

    float ls = 0.f;
    for (int t = tid; t < count; t += 256) {
        float e = __expf(s[t] - M);
        s[t] = e;
        ls += e;
    }
    #pragma unroll
    for (int off = 16; off; off >>= 1) ls += __shfl_xor_sync(0xffffffffu, ls, off);
    if ((tid & 31) == 0) red[tid >> 5] = ls;
    bins[tid] = 0.f;             // tid covers 0..255 == NCHAR
    __syncthreads();
    float S = 0.f;
    #pragma unroll
    for (int k = 0; k < 8; k++) S += red[k];
    float inv = 1.f / S;

    float* WR = g_wr + (size_t)i * XPAD;
    for (int t = tid; t < L_; t += 256) {
        float w = 0.f;
        if (t < count) {
            w = s[t] * inv;
            atomicAdd(&bins[data[(size_t)b * L_ + t] & (NCHAR - 1)], w);
        }
        WR[NCHAR + t] = w;
    }
    for (int r = XROWS + tid; r < XPAD; r += 256) WR[r] = 0.f;   // pad tail
    __syncthreads();
    WR[tid] = bins[tid];
}

// ---------------------------------------------------------------------------
// Kernel 6: Y = WR @ X (NN GEMM). M=256 (i), N=512 (e), K=1280 (r).
// Tiles 64x64, BK=16, 4x4 blocking.
// ---------------------------------------------------------------------------
__global__ void y_gemm_kernel() {
    int m0 = blockIdx.y * BM;
    int n0 = blockIdx.x * BN;

    __shared__ float As[BK][BM + 4];
    __shared__ float Bs[BK][BN + 4];

    int tid  = threadIdx.x;          // 256
    int lrow = tid >> 2;             // 0..63
    int lcol = (tid & 3) * 4;        // 0,4,8,12
    int br = tid >> 4;               // 0..15 (B tile row)
    int bc = (tid & 15) * 4;         // 0..60 (B tile col)
    int ty = tid >> 4;
    int tx = tid & 15;

    float acc[4][4] = {};

    for (int k0 = 0; k0 < XPAD; k0 += BK) {
        // A tile: WR[m0+lrow][k0+lcol..+3] -> transposed into As[k][i]
        float4 av = *(const float4*)(g_wr + (size_t)(m0 + lrow) * XPAD + k0 + lcol);
        As[lcol + 0][lrow] = av.x; As[lcol + 1][lrow] = av.y;
        As[lcol + 2][lrow] = av.z; As[lcol + 3][lrow] = av.w;

        // B tile: X[k0+br][n0+bc..+3] -> direct
        float4 bv4 = *(const float4*)(g_X + (size_t)(k0 + br) * DM + n0 + bc);
        *(float4*)&Bs[br][bc] = bv4;

        __syncthreads();

        #pragma unroll
        for (int kk = 0; kk < BK; kk++) {
            float4 a4 = *(const float4*)&As[kk][ty * 4];
            float4 b4 = *(const float4*)&Bs[kk][tx * 4];
            float a[4] = {a4.x, a4.y, a4.z, a4.w};
            float b[4] = {b4.x, b4.y, b4.z, b4.w};
            #pragma unroll
            for (int ii = 0; ii < 4; ii++)
                #pragma unroll
                for (int jj = 0; jj < 4; jj++)
                    acc[ii][jj] += a[ii] * b[jj];
        }
        __syncthreads();
    }

    #pragma unroll
    for (int ii = 0; ii < 4; ii++) {
        int r = m0 + ty * 4 + ii;
        #pragma unroll
        for (int jj = 0; jj < 4; jj++)
            g_y[(size_t)r * DM + n0 + tx * 4 + jj] = acc[ii][jj];
    }
}

// ---------------------------------------------------------------------------
// Kernel 7 (fused): ctx[b] = per-head Wv_h @ y[h,b] + bv, then MLP head.
// One block per batch, 256 threads (8 warps). Warp w == head w for ctx rows.
// ---------------------------------------------------------------------------
__global__ void ctx_mlp_kernel(const float* __restrict__ Wv,
                               const float* __restrict__ bv,
                               const float* __restrict__ W1,
                               const float* __restrict__ b1,
                               const float* __restrict__ W2,
                               const float* __restrict__ b2,
                               float* __restrict__ out) {
    int b = blockIdx.x;
    __shared__ float ys[NH][DM];     // 16 KB
    __shared__ float cs[DM];
    __shared__ float hs[DM];
    __shared__ float o8[8];
    int tid = threadIdx.x;           // 256
    int w = tid >> 5, lane = tid & 31;

    for (int idx = tid; idx < NH * DM; idx += 256) {
        int h = idx >> 9, e = idx & 511;
        ys[h][e] = g_y[(size_t)(h * B_ + b) * DM + e];
    }
    __syncthreads();

    // ctx rows j = w*64 .. w*64+63; head h == w
    const float* yv = ys[w];
    for (int j = w * DH; j < w * DH + DH; j++) {
        const float* wr = Wv + (size_t)j * DM;
        float s = 0.f;
        #pragma unroll
        for (int e0 = lane * 4; e0 < DM; e0 += 128) {
            float4 a = *(const float4*)(wr + e0);
            float4 y4 = *(const float4*)(yv + e0);
            s += a.x * y4.x + a.y * y4.y + a.z * y4.z + a.w * y4.w;
        }
        #pragma unroll
        for (int off = 16; off; off >>= 1) s += __shfl_xor_sync(0xffffffffu, s, off);
        if (lane == 0) cs[j] = s + bv[j];
    }
    __syncthreads();

    // layer 1: hs = lrelu(W1 @ cs + b1)
    for (int j = w * DH; j < w * DH + DH; j++) {
        const float* wr = W1 + (size_t)j * DM;
        float s = 0.f;
        #pragma unroll
        for (int e0 = lane * 4; e0 < DM; e0 += 128) {
            float4 a = *(const float4*)(wr + e0);
            float4 c4 = *(const float4*)(cs + e0);
            s += a.x * c4.x + a.y * c4.y + a.z * c4.z + a.w * c4.w;
        }
        #pragma unroll
        for (int off = 16; off; off >>= 1) s += __shfl_xor_sync(0xffffffffu, s, off);
        if (lane == 0) {
            float v = s + b1[j];
            hs[j] = (v > 0.f) ? v : 0.01f * v;
        }
    }
    __syncthreads();

    // layer 2: 8 outputs, warp w -> row w
    {
        const float* wr = W2 + (size_t)w * DM;
        float s = 0.f;
        #pragma unroll
        for (int e0 = lane * 4; e0 < DM; e0 += 128) {
            float4 a = *(const float4*)(wr + e0);
            float4 h4 = *(const float4*)(hs + e0);
            s += a.x * h4.x + a.y * h4.y + a.z * h4.z + a.w * h4.w;
        }
        #pragma unroll
        for (int off = 16; off; off >>= 1) s += __shfl_xor_sync(0xffffffffu, s, off);
        if (lane == 0) {
            float v = s + b2[w];
            o8[w] = (v > 0.f) ? v : 0.f;
        }
    }
    __syncthreads();
    if (tid == 0) {
        float mv = 0.f;
        #pragma unroll
        for (int k = 0; k < 8; k++) mv += o8[k];
        mv *= 0.125f;
        out[b] = (mv > 0.f) ? mv : 0.01f * mv;
    }
}

// ---------------------------------------------------------------------------
extern "C" void kernel_launch(void* const* d_in, const int* in_sizes, int n_in,
                              void* d_out, int out_size) {
    const int* data    = (const int*)d_in[0];    // int32 (JAX x64 disabled)
    const int* lengths = (const int*)d_in[1];
    const float* emb = (const float*)d_in[2];
    const float* Wq  = (const float*)d_in[3];
    const float* bq  = (const float*)d_in[4];
    const float* Wk  = (const float*)d_in[5];
    // d_in[6] = bk: drops out of softmax (constant shift per row)
    const float* Wv  = (const float*)d_in[7];
    const float* bv  = (const float*)d_in[8];
    const float* W1  = (const float*)d_in[9];
    const float* b1  = (const float*)d_in[10];
    const float* W2  = (const float*)d_in[11];
    const float* b2  = (const float*)d_in[12];
    float* out = (float*)d_out;

    build_x_kernel<<<(XPAD * DM + 255) / 256, 256>>>(emb);
    q_kernel<<<B_, DM>>>(data, lengths, emb, Wq, bq);
    u_kernel<<<dim3(NH, B_), 256>>>(Wk);
    d_gemm_kernel<<<dim3(XPAD / BN, (NH * B_) / BM), 256>>>();
    softmax_bin_kernel<<<dim3(NH, B_), 256>>>(data, lengths);
    y_gemm_kernel<<<dim3(DM / BN, (NH * B_) / BM), 256>>>();
    ctx_mlp_kernel<<<B_, 256>>>(Wv, bv, W1, b1, W2, b2, out);
}

// round 5
// speedup vs baseline: 1.9107x; 1.9107x over previous
#include <cuda_runtime.h>
#include <math_constants.h>

// Problem constants
#define B_    32
#define L_    1000
#define NCHAR 256
#define DM    512
#define NH    8
#define DH    64
#define XROWS (NCHAR + L_)   // 1256
#define XPAD  1280           // padded row count (multiple of 64), pad rows zero
#define NI    (NH * B_)      // 256 (h,b) pairs
#define LN10000 9.210340371976184f

// Split-K factors
#define DSPLIT 4
#define DCHUNK (DM / DSPLIT)      // 128
#define YSPLIT 8
#define YCHUNK (XPAD / YSPLIT)    // 160

// Scratch (device globals: no allocation allowed)
__device__ float g_X  [XPAD * DM];           // [emb(256) ; pe(1000) ; zeros(24)]
__device__ float g_u  [NI * DM];             // U[i=h*32+b][e] = q[b,h] @ Wk_head
__device__ float g_dotp[DSPLIT][NI * XPAD];  // K-split partials of D = U @ X^T * scale
__device__ float g_wr [NI * XPAD];           // WR[i][r] softmax weight rows
__device__ float g_yp [YSPLIT][NI * DM];     // K-split partials of Y = WR @ X

// ---------------------------------------------------------------------------
// Kernel 1: build X = [emb(256,512) ; pe(1000,512) ; zeros]
// ---------------------------------------------------------------------------
__global__ void build_x_kernel(const float* __restrict__ emb) {
    int i = blockIdx.x * blockDim.x + threadIdx.x;
    if (i >= XPAD * DM) return;
    int r = i >> 9;       // /512
    int e = i & 511;
    float v = 0.f;
    if (r < NCHAR) {
        v = emb[i];
    } else if (r < XROWS) {
        int t = r - NCHAR;
        int pair = e >> 1;
        float div = expf((float)(2 * pair) * (-LN10000 / (float)DM));
        float ang = (float)t * div;
        v = (e & 1) ? cosf(ang) : sinf(ang);
    }
    g_X[i] = v;
}

// ---------------------------------------------------------------------------
// Kernel 2 (fused q+u): per (h,b) block computes
//   x_b = emb[c_p] + pe_p                        (shared)
//   qh[d] = Wq[h*64+d] . x_b + bq[h*64+d]        (64 values, shared)
//   U[i][e] = sum_d qh[d] * Wk[h*64+d][e]        (512 outputs)
// grid (NH, B_), 256 threads.
// ---------------------------------------------------------------------------
__global__ void u_fused_kernel(const int* __restrict__ data,
                               const int* __restrict__ lengths,
                               const float* __restrict__ emb,
                               const float* __restrict__ Wq,
                               const float* __restrict__ bq,
                               const float* __restrict__ Wk) {
    int h = blockIdx.x, b = blockIdx.y;
    __shared__ float xs[DM];
    __shared__ float qs[DH];
    int tid = threadIdx.x;           // 256
    int w = tid >> 5, lane = tid & 31;

    int p = lengths[b] - 1;
    if (p < 0) p = 0;
    if (p >= L_) p = L_ - 1;
    int c = data[(size_t)b * L_ + p] & (NCHAR - 1);

    for (int e = tid; e < DM; e += 256) {
        int pair = e >> 1;
        float div = expf((float)(2 * pair) * (-LN10000 / (float)DM));
        float ang = (float)p * div;
        float pe = (e & 1) ? cosf(ang) : sinf(ang);
        xs[e] = emb[(size_t)c * DM + e] + pe;
    }
    __syncthreads();

    // qh rows: warp w handles d = w*8 .. w*8+7
    for (int d = w * 8; d < w * 8 + 8; d++) {
        int j = h * DH + d;
        const float* wr = Wq + (size_t)j * DM;
        float s = 0.f;
        #pragma unroll
        for (int e0 = lane * 4; e0 < DM; e0 += 128) {
            float4 a = *(const float4*)(wr + e0);
            float4 x4 = *(const float4*)(xs + e0);
            s += a.x * x4.x + a.y * x4.y + a.z * x4.z + a.w * x4.w;
        }
        #pragma unroll
        for (int off = 16; off; off >>= 1) s += __shfl_xor_sync(0xffffffffu, s, off);
        if (lane == 0) qs[d] = s + bq[j];
    }
    __syncthreads();

    // U row: thread owns 2 consecutive e
    int e0 = tid * 2;
    float a0 = 0.f, a1 = 0.f;
    const float* Wbase = Wk + (size_t)(h * DH) * DM;
    #pragma unroll 8
    for (int d = 0; d < DH; d++) {
        float qd = qs[d];
        float2 wv = *(const float2*)(Wbase + (size_t)d * DM + e0);
        a0 += qd * wv.x;
        a1 += qd * wv.y;
    }
    *(float2*)(g_u + (size_t)(h * B_ + b) * DM + e0) = make_float2(a0, a1);
}

// ---------------------------------------------------------------------------
// Kernel 3: D partials = U @ X^T (NT GEMM, scaled), K split by DSPLIT.
// grid (XPAD/64, NI/64, DSPLIT), 256 threads, 64x64 tile, 4x4 blocking.
// ---------------------------------------------------------------------------
#define BM 64
#define BN 64
#define BK 16
__global__ void d_gemm_kernel() {
    int m0 = blockIdx.y * BM;
    int n0 = blockIdx.x * BN;
    int kb = blockIdx.z * DCHUNK;

    __shared__ float As[BK][BM + 4];
    __shared__ float Bs[BK][BN + 4];

    int tid  = threadIdx.x;          // 256
    int lrow = tid >> 2;             // 0..63
    int lcol = (tid & 3) * 4;        // 0,4,8,12
    int ty = tid >> 4;               // 0..15
    int tx = tid & 15;               // 0..15

    float acc[4][4] = {};

    for (int k0 = kb; k0 < kb + DCHUNK; k0 += BK) {
        float4 av = *(const float4*)(g_u + (size_t)(m0 + lrow) * DM + k0 + lcol);
        As[lcol + 0][lrow] = av.x; As[lcol + 1][lrow] = av.y;
        As[lcol + 2][lrow] = av.z; As[lcol + 3][lrow] = av.w;

        float4 bv4 = *(const float4*)(g_X + (size_t)(n0 + lrow) * DM + k0 + lcol);
        Bs[lcol + 0][lrow] = bv4.x; Bs[lcol + 1][lrow] = bv4.y;
        Bs[lcol + 2][lrow] = bv4.z; Bs[lcol + 3][lrow] = bv4.w;

        __syncthreads();

        #pragma unroll
        for (int kk = 0; kk < BK; kk++) {
            float4 a4 = *(const float4*)&As[kk][ty * 4];
            float4 b4 = *(const float4*)&Bs[kk][tx * 4];
            float a[4] = {a4.x, a4.y, a4.z, a4.w};
            float b[4] = {b4.x, b4.y, b4.z, b4.w};
            #pragma unroll
            for (int i = 0; i < 4; i++)
                #pragma unroll
                for (int j = 0; j < 4; j++)
                    acc[i][j] += a[i] * b[j];
        }
        __syncthreads();
    }

    float* outp = g_dotp[blockIdx.z];
    #pragma unroll
    for (int i = 0; i < 4; i++) {
        int r = m0 + ty * 4 + i;
        #pragma unroll
        for (int j = 0; j < 4; j++) {
            int c = n0 + tx * 4 + j;
            outp[(size_t)r * XPAD + c] = acc[i][j] * 0.125f;  // 1/sqrt(64)
        }
    }
}

// ---------------------------------------------------------------------------
// Kernel 4: per (h,b) softmax over valid positions + char binning.
// Sums the DSPLIT partials of D inline.
// WR[i][c]      = sum of weights of positions with char c   (c < 256)
// WR[i][256+t]  = weight of position t (0 if t >= count); tail zeros.
// ---------------------------------------------------------------------------
__global__ void softmax_bin_kernel(const int* __restrict__ data,
                                   const int* __restrict__ lengths) {
    int h = blockIdx.x;
    int b = blockIdx.y;
    int i = h * B_ + b;
    __shared__ float s[L_];
    __shared__ float bins[NCHAR];
    __shared__ float red[8];

    int tid = threadIdx.x;       // 256
    int count = lengths[b];
    if (count < 1) count = 1;
    if (count > L_) count = L_;

    size_t base = (size_t)i * XPAD;

    float lm = -CUDART_INF_F;
    for (int t = tid; t < count; t += 256) {
        int c = data[(size_t)b * L_ + t] & (NCHAR - 1);
        float v = 0.f;
        #pragma unroll
        for (int z = 0; z < DSPLIT; z++)
            v += g_dotp[z][base + NCHAR + t] + g_dotp[z][base + c];
        s[t] = v;
        lm = fmaxf(lm, v);
    }
    #pragma unroll
    for (int off = 16; off; off >>= 1) lm = fmaxf(lm, __shfl_xor_sync(0xffffffffu, lm, off));
    if ((tid & 31) == 0) red[tid >> 5] = lm;
    __syncthreads();
    float M = -CUDART_INF_F;
    #pragma unroll
    for (int k = 0; k < 8; k++) M = fmaxf(M, red[k]);
    __syncthreads();

    float ls = 0.f;
    for (int t = tid; t < count; t += 256) {
        float e = __expf(s[t] - M);
        s[t] = e;
        ls += e;
    }
    #pragma unroll
    for (int off = 16; off; off >>= 1) ls += __shfl_xor_sync(0xffffffffu, ls, off);
    if ((tid & 31) == 0) red[tid >> 5] = ls;
    bins[tid] = 0.f;             // tid covers 0..255 == NCHAR
    __syncthreads();
    float S = 0.f;
    #pragma unroll
    for (int k = 0; k < 8; k++) S += red[k];
    float inv = 1.f / S;

    float* WR = g_wr + base;
    for (int t = tid; t < L_; t += 256) {
        float w = 0.f;
        if (t < count) {
            w = s[t] * inv;
            atomicAdd(&bins[data[(size_t)b * L_ + t] & (NCHAR - 1)], w);
        }
        WR[NCHAR + t] = w;
    }
    for (int r = XROWS + tid; r < XPAD; r += 256) WR[r] = 0.f;   // pad tail
    __syncthreads();
    WR[tid] = bins[tid];
}

// ---------------------------------------------------------------------------
// Kernel 5: Y partials = WR @ X (NN GEMM), K split by YSPLIT.
// grid (DM/64, NI/64, YSPLIT), 256 threads, 64x64 tile, 4x4 blocking.
// ---------------------------------------------------------------------------
__global__ void y_gemm_kernel() {
    int m0 = blockIdx.y * BM;
    int n0 = blockIdx.x * BN;
    int kb = blockIdx.z * YCHUNK;

    __shared__ float As[BK][BM + 4];
    __shared__ float Bs[BK][BN + 4];

    int tid  = threadIdx.x;          // 256
    int lrow = tid >> 2;             // 0..63
    int lcol = (tid & 3) * 4;        // 0,4,8,12
    int br = tid >> 4;               // 0..15 (B tile row)
    int bc = (tid & 15) * 4;         // 0..60 (B tile col)
    int ty = tid >> 4;
    int tx = tid & 15;

    float acc[4][4] = {};

    for (int k0 = kb; k0 < kb + YCHUNK; k0 += BK) {
        // A tile: WR[m0+lrow][k0+lcol..+3] -> transposed into As[k][i]
        float4 av = *(const float4*)(g_wr + (size_t)(m0 + lrow) * XPAD + k0 + lcol);
        As[lcol + 0][lrow] = av.x; As[lcol + 1][lrow] = av.y;
        As[lcol + 2][lrow] = av.z; As[lcol + 3][lrow] = av.w;

        // B tile: X[k0+br][n0+bc..+3] -> direct
        float4 bv4 = *(const float4*)(g_X + (size_t)(k0 + br) * DM + n0 + bc);
        *(float4*)&Bs[br][bc] = bv4;

        __syncthreads();

        #pragma unroll
        for (int kk = 0; kk < BK; kk++) {
            float4 a4 = *(const float4*)&As[kk][ty * 4];
            float4 b4 = *(const float4*)&Bs[kk][tx * 4];
            float a[4] = {a4.x, a4.y, a4.z, a4.w};
            float b[4] = {b4.x, b4.y, b4.z, b4.w};
            #pragma unroll
            for (int ii = 0; ii < 4; ii++)
                #pragma unroll
                for (int jj = 0; jj < 4; jj++)
                    acc[ii][jj] += a[ii] * b[jj];
        }
        __syncthreads();
    }

    float* outp = g_yp[blockIdx.z];
    #pragma unroll
    for (int ii = 0; ii < 4; ii++) {
        int r = m0 + ty * 4 + ii;
        #pragma unroll
        for (int jj = 0; jj < 4; jj++)
            outp[(size_t)r * DM + n0 + tx * 4 + jj] = acc[ii][jj];
    }
}

// ---------------------------------------------------------------------------
// Kernel 6 (fused): sum Y partials; ctx = per-head Wv_h @ y + bv; MLP head.
// One block per batch, 256 threads (8 warps). Warp w == head w for ctx rows.
// ---------------------------------------------------------------------------
__global__ void ctx_mlp_kernel(const float* __restrict__ Wv,
                               const float* __restrict__ bv,
                               const float* __restrict__ W1,
                               const float* __restrict__ b1,
                               const float* __restrict__ W2,
                               const float* __restrict__ b2,
                               float* __restrict__ out) {
    int b = blockIdx.x;
    __shared__ float ys[NH][DM];     // 16 KB
    __shared__ float cs[DM];
    __shared__ float hs[DM];
    __shared__ float o8[8];
    int tid = threadIdx.x;           // 256
    int w = tid >> 5, lane = tid & 31;

    for (int idx = tid; idx < NH * DM; idx += 256) {
        int h = idx >> 9, e = idx & 511;
        size_t off = (size_t)(h * B_ + b) * DM + e;
        float v = 0.f;
        #pragma unroll
        for (int z = 0; z < YSPLIT; z++) v += g_yp[z][off];
        ys[h][e] = v;
    }
    __syncthreads();

    // ctx rows j = w*64 .. w*64+63; head h == w
    const float* yv = ys[w];
    for (int j = w * DH; j < w * DH + DH; j++) {
        const float* wr = Wv + (size_t)j * DM;
        float s = 0.f;
        #pragma unroll
        for (int e0 = lane * 4; e0 < DM; e0 += 128) {
            float4 a = *(const float4*)(wr + e0);
            float4 y4 = *(const float4*)(yv + e0);
            s += a.x * y4.x + a.y * y4.y + a.z * y4.z + a.w * y4.w;
        }
        #pragma unroll
        for (int off = 16; off; off >>= 1) s += __shfl_xor_sync(0xffffffffu, s, off);
        if (lane == 0) cs[j] = s + bv[j];
    }
    __syncthreads();

    // layer 1: hs = lrelu(W1 @ cs + b1)
    for (int j = w * DH; j < w * DH + DH; j++) {
        const float* wr = W1 + (size_t)j * DM;
        float s = 0.f;
        #pragma unroll
        for (int e0 = lane * 4; e0 < DM; e0 += 128) {
            float4 a = *(const float4*)(wr + e0);
            float4 c4 = *(const float4*)(cs + e0);
            s += a.x * c4.x + a.y * c4.y + a.z * c4.z + a.w * c4.w;
        }
        #pragma unroll
        for (int off = 16; off; off >>= 1) s += __shfl_xor_sync(0xffffffffu, s, off);
        if (lane == 0) {
            float v = s + b1[j];
            hs[j] = (v > 0.f) ? v : 0.01f * v;
        }
    }
    __syncthreads();

    // layer 2: 8 outputs, warp w -> row w
    {
        const float* wr = W2 + (size_t)w * DM;
        float s = 0.f;
        #pragma unroll
        for (int e0 = lane * 4; e0 < DM; e0 += 128) {
            float4 a = *(const float4*)(wr + e0);
            float4 h4 = *(const float4*)(hs + e0);
            s += a.x * h4.x + a.y * h4.y + a.z * h4.z + a.w * h4.w;
        }
        #pragma unroll
        for (int off = 16; off; off >>= 1) s += __shfl_xor_sync(0xffffffffu, s, off);
        if (lane == 0) {
            float v = s + b2[w];
            o8[w] = (v > 0.f) ? v : 0.f;
        }
    }
    __syncthreads();
    if (tid == 0) {
        float mv = 0.f;
        #pragma unroll
        for (int k = 0; k < 8; k++) mv += o8[k];
        mv *= 0.125f;
        out[b] = (mv > 0.f) ? mv : 0.01f * mv;
    }
}

// ---------------------------------------------------------------------------
extern "C" void kernel_launch(void* const* d_in, const int* in_sizes, int n_in,
                              void* d_out, int out_size) {
    const int* data    = (const int*)d_in[0];    // int32 (JAX x64 disabled)
    const int* lengths = (const int*)d_in[1];
    const float* emb = (const float*)d_in[2];
    const float* Wq  = (const float*)d_in[3];
    const float* bq  = (const float*)d_in[4];
    const float* Wk  = (const float*)d_in[5];
    // d_in[6] = bk: drops out of softmax (constant shift per row)
    const float* Wv  = (const float*)d_in[7];
    const float* bv  = (const float*)d_in[8];
    const float* W1  = (const float*)d_in[9];
    const float* b1  = (const float*)d_in[10];
    const float* W2  = (const float*)d_in[11];
    const float* b2  = (const float*)d_in[12];
    float* out = (float*)d_out;

    build_x_kernel<<<(XPAD * DM + 255) / 256, 256>>>(emb);
    u_fused_kernel<<<dim3(NH, B_), 256>>>(data, lengths, emb, Wq, bq, Wk);
    d_gemm_kernel<<<dim3(XPAD / BN, NI / BM, DSPLIT), 256>>>();
    softmax_bin_kernel<<<dim3(NH, B_), 256>>>(data, lengths);
    y_gemm_kernel<<<dim3(DM / BN, NI / BM, YSPLIT), 256>>>();
    ctx_mlp_kernel<<<B_, 256>>>(Wv, bv, W1, b1, W2, b2, out);
}

// round 6
// speedup vs baseline: 2.4951x; 1.3059x over previous
#include <cuda_runtime.h>
#include <math_constants.h>

// Problem constants
#define B_    32
#define L_    1000
#define NCHAR 256
#define DM    512
#define NH    8
#define DH    64
#define XROWS (NCHAR + L_)   // 1256
#define XPAD  1280           // padded row count (multiple of 64), pad rows zero
#define NI    (NH * B_)      // 256 (h,b) pairs
#define LN10000 9.210340371976184f

// Split-K factors
#define DSPLIT 4
#define DCHUNK (DM / DSPLIT)      // 128
#define YSPLIT 8
#define YCHUNK (XPAD / YSPLIT)    // 160

// Scratch (device globals: no allocation allowed)
__device__ float g_X  [XPAD * DM];           // [emb(256) ; pe(1000) ; zeros(24)]
__device__ float g_u  [NI * DM];             // U[i=h*32+b][e] = q[b,h] @ Wk_head
__device__ float g_dotp[DSPLIT][NI * XPAD];  // K-split partials of D = U @ X^T * scale
__device__ float g_wr [NI * XPAD];           // WR[i][r] softmax weight rows (pad stays 0)
__device__ float g_yp [YSPLIT][NI * DM];     // K-split partials of Y = WR @ X
__device__ float g_ctx[B_ * DM];             // attention context at last valid position

// ---------------------------------------------------------------------------
// Kernel 1 (merged): blocks [0, XPAD) build g_X rows; blocks [XPAD, XPAD+NI)
// compute U rows (fused q+u per (h,b)).
// ---------------------------------------------------------------------------
__global__ void setup_kernel(const int* __restrict__ data,
                             const int* __restrict__ lengths,
                             const float* __restrict__ emb,
                             const float* __restrict__ Wq,
                             const float* __restrict__ bq,
                             const float* __restrict__ Wk) {
    int blk = blockIdx.x;
    int tid = threadIdx.x;           // 256

    if (blk < XPAD) {
        // --- build one row of g_X; thread owns pair (2 elems) ---
        int r = blk;
        float2* dst = (float2*)(g_X + (size_t)r * DM);
        if (r < NCHAR) {
            dst[tid] = ((const float2*)(emb + (size_t)r * DM))[tid];
        } else if (r < XROWS) {
            int t = r - NCHAR;
            float div = expf((float)(2 * tid) * (-LN10000 / (float)DM));
            float s, c;
            sincosf((float)t * div, &s, &c);
            dst[tid] = make_float2(s, c);
        } else {
            dst[tid] = make_float2(0.f, 0.f);
        }
        return;
    }

    // --- fused q+u for i = blk - XPAD ---
    int i = blk - XPAD;
    int h = i >> 5;                  // i = h*32 + b
    int b = i & 31;
    __shared__ float xs[DM];
    __shared__ float qs[DH];
    int w = tid >> 5, lane = tid & 31;

    int p = lengths[b] - 1;
    if (p < 0) p = 0;
    if (p >= L_) p = L_ - 1;
    int c = data[(size_t)b * L_ + p] & (NCHAR - 1);

    for (int e = tid; e < DM; e += 256) {
        int pair = e >> 1;
        float div = expf((float)(2 * pair) * (-LN10000 / (float)DM));
        float ang = (float)p * div;
        float pe = (e & 1) ? cosf(ang) : sinf(ang);
        xs[e] = emb[(size_t)c * DM + e] + pe;
    }
    __syncthreads();

    // qh rows: warp w handles d = w*8 .. w*8+7
    for (int d = w * 8; d < w * 8 + 8; d++) {
        int j = h * DH + d;
        const float* wr = Wq + (size_t)j * DM;
        float s = 0.f;
        #pragma unroll
        for (int e0 = lane * 4; e0 < DM; e0 += 128) {
            float4 a = *(const float4*)(wr + e0);
            float4 x4 = *(const float4*)(xs + e0);
            s += a.x * x4.x + a.y * x4.y + a.z * x4.z + a.w * x4.w;
        }
        #pragma unroll
        for (int off = 16; off; off >>= 1) s += __shfl_xor_sync(0xffffffffu, s, off);
        if (lane == 0) qs[d] = s + bq[j];
    }
    __syncthreads();

    // U row: thread owns 2 consecutive e
    int e0 = tid * 2;
    float a0 = 0.f, a1 = 0.f;
    const float* Wbase = Wk + (size_t)(h * DH) * DM;
    #pragma unroll 8
    for (int d = 0; d < DH; d++) {
        float qd = qs[d];
        float2 wv = *(const float2*)(Wbase + (size_t)d * DM + e0);
        a0 += qd * wv.x;
        a1 += qd * wv.y;
    }
    *(float2*)(g_u + (size_t)i * DM + e0) = make_float2(a0, a1);
}

// ---------------------------------------------------------------------------
// Kernel 2: D partials = U @ X^T (NT GEMM, scaled), K split by DSPLIT.
// Double-buffered smem tiles. grid (XPAD/64, NI/64, DSPLIT), 256 threads.
// ---------------------------------------------------------------------------
#define BM 64
#define BN 64
#define BK 16
__global__ void d_gemm_kernel() {
    int m0 = blockIdx.y * BM;
    int n0 = blockIdx.x * BN;
    int kb = blockIdx.z * DCHUNK;

    __shared__ float As[2][BK][BM + 4];
    __shared__ float Bs[2][BK][BN + 4];

    int tid  = threadIdx.x;          // 256
    int lrow = tid >> 2;             // 0..63
    int lcol = (tid & 3) * 4;        // 0,4,8,12
    int ty = tid >> 4;               // 0..15
    int tx = tid & 15;               // 0..15

    const float* Aptr = g_u + (size_t)(m0 + lrow) * DM + lcol;
    const float* Bptr = g_X + (size_t)(n0 + lrow) * DM + lcol;

    float4 a_n = *(const float4*)(Aptr + kb);
    float4 b_n = *(const float4*)(Bptr + kb);
    As[0][lcol + 0][lrow] = a_n.x; As[0][lcol + 1][lrow] = a_n.y;
    As[0][lcol + 2][lrow] = a_n.z; As[0][lcol + 3][lrow] = a_n.w;
    Bs[0][lcol + 0][lrow] = b_n.x; Bs[0][lcol + 1][lrow] = b_n.y;
    Bs[0][lcol + 2][lrow] = b_n.z; Bs[0][lcol + 3][lrow] = b_n.w;
    __syncthreads();

    float acc[4][4] = {};
    const int NIT = DCHUNK / BK;     // 8

    for (int it = 0; it < NIT; it++) {
        int cur = it & 1, nxt = cur ^ 1;
        if (it + 1 < NIT) {
            a_n = *(const float4*)(Aptr + kb + (it + 1) * BK);
            b_n = *(const float4*)(Bptr + kb + (it + 1) * BK);
        }
        #pragma unroll
        for (int kk = 0; kk < BK; kk++) {
            float4 a4 = *(const float4*)&As[cur][kk][ty * 4];
            float4 b4 = *(const float4*)&Bs[cur][kk][tx * 4];
            float a[4] = {a4.x, a4.y, a4.z, a4.w};
            float b[4] = {b4.x, b4.y, b4.z, b4.w};
            #pragma unroll
            for (int i = 0; i < 4; i++)
                #pragma unroll
                for (int j = 0; j < 4; j++)
                    acc[i][j] += a[i] * b[j];
        }
        if (it + 1 < NIT) {
            As[nxt][lcol + 0][lrow] = a_n.x; As[nxt][lcol + 1][lrow] = a_n.y;
            As[nxt][lcol + 2][lrow] = a_n.z; As[nxt][lcol + 3][lrow] = a_n.w;
            Bs[nxt][lcol + 0][lrow] = b_n.x; Bs[nxt][lcol + 1][lrow] = b_n.y;
            Bs[nxt][lcol + 2][lrow] = b_n.z; Bs[nxt][lcol + 3][lrow] = b_n.w;
            __syncthreads();
        }
    }

    float* outp = g_dotp[blockIdx.z];
    #pragma unroll
    for (int i = 0; i < 4; i++) {
        int r = m0 + ty * 4 + i;
        #pragma unroll
        for (int j = 0; j < 4; j++) {
            int c = n0 + tx * 4 + j;
            outp[(size_t)r * XPAD + c] = acc[i][j] * 0.125f;  // 1/sqrt(64)
        }
    }
}

// ---------------------------------------------------------------------------
// Kernel 3: per (h,b) softmax over valid positions + char binning.
// Char-dot partials pre-summed into shared dch[256]; position partials
// summed with coalesced loads.
// ---------------------------------------------------------------------------
__global__ void softmax_bin_kernel(const int* __restrict__ data,
                                   const int* __restrict__ lengths) {
    int h = blockIdx.x;
    int b = blockIdx.y;
    int i = h * B_ + b;
    __shared__ float s[L_];
    __shared__ float dch[NCHAR];
    __shared__ float bins[NCHAR];
    __shared__ float red[8];

    int tid = threadIdx.x;       // 256
    int count = lengths[b];
    if (count < 1) count = 1;
    if (count > L_) count = L_;

    size_t base = (size_t)i * XPAD;

    // summed char dots (coalesced)
    {
        float v = 0.f;
        #pragma unroll
        for (int z = 0; z < DSPLIT; z++) v += g_dotp[z][base + tid];
        dch[tid] = v;
        bins[tid] = 0.f;
    }
    __syncthreads();

    float lm = -CUDART_INF_F;
    for (int t = tid; t < count; t += 256) {
        int c = data[(size_t)b * L_ + t] & (NCHAR - 1);
        float v = dch[c];
        #pragma unroll
        for (int z = 0; z < DSPLIT; z++) v += g_dotp[z][base + NCHAR + t];
        s[t] = v;
        lm = fmaxf(lm, v);
    }
    #pragma unroll
    for (int off = 16; off; off >>= 1) lm = fmaxf(lm, __shfl_xor_sync(0xffffffffu, lm, off));
    if ((tid & 31) == 0) red[tid >> 5] = lm;
    __syncthreads();
    float M = -CUDART_INF_F;
    #pragma unroll
    for (int k = 0; k < 8; k++) M = fmaxf(M, red[k]);
    __syncthreads();

    float ls = 0.f;
    for (int t = tid; t < count; t += 256) {
        float e = __expf(s[t] - M);
        s[t] = e;
        ls += e;
    }
    #pragma unroll
    for (int off = 16; off; off >>= 1) ls += __shfl_xor_sync(0xffffffffu, ls, off);
    if ((tid & 31) == 0) red[tid >> 5] = ls;
    __syncthreads();
    float S = 0.f;
    #pragma unroll
    for (int k = 0; k < 8; k++) S += red[k];
    float inv = 1.f / S;

    float* WR = g_wr + base;
    for (int t = tid; t < L_; t += 256) {
        float w = 0.f;
        if (t < count) {
            w = s[t] * inv;
            atomicAdd(&bins[data[(size_t)b * L_ + t] & (NCHAR - 1)], w);
        }
        WR[NCHAR + t] = w;
    }
    __syncthreads();
    WR[tid] = bins[tid];
    // pad rows of g_X are zero, so WR[XROWS..XPAD) never contributes (stays 0)
}

// ---------------------------------------------------------------------------
// Kernel 4: Y partials = WR @ X (NN GEMM), K split by YSPLIT. Double-buffered.
// grid (DM/64, NI/64, YSPLIT), 256 threads.
// ---------------------------------------------------------------------------
__global__ void y_gemm_kernel() {
    int m0 = blockIdx.y * BM;
    int n0 = blockIdx.x * BN;
    int kb = blockIdx.z * YCHUNK;

    __shared__ float As[2][BK][BM + 4];
    __shared__ float Bs[2][BK][BN + 4];

    int tid  = threadIdx.x;          // 256
    int lrow = tid >> 2;             // 0..63
    int lcol = (tid & 3) * 4;        // 0,4,8,12
    int br = tid >> 4;               // 0..15 (B tile row)
    int bc = (tid & 15) * 4;         // 0..60 (B tile col)
    int ty = tid >> 4;
    int tx = tid & 15;

    const float* Aptr = g_wr + (size_t)(m0 + lrow) * XPAD + lcol;

    float4 a_n = *(const float4*)(Aptr + kb);
    float4 b_n = *(const float4*)(g_X + (size_t)(kb + br) * DM + n0 + bc);
    As[0][lcol + 0][lrow] = a_n.x; As[0][lcol + 1][lrow] = a_n.y;
    As[0][lcol + 2][lrow] = a_n.z; As[0][lcol + 3][lrow] = a_n.w;
    *(float4*)&Bs[0][br][bc] = b_n;
    __syncthreads();

    float acc[4][4] = {};
    const int NIT = YCHUNK / BK;     // 10

    for (int it = 0; it < NIT; it++) {
        int cur = it & 1, nxt = cur ^ 1;
        if (it + 1 < NIT) {
            int k0 = kb + (it + 1) * BK;
            a_n = *(const float4*)(Aptr + k0);
            b_n = *(const float4*)(g_X + (size_t)(k0 + br) * DM + n0 + bc);
        }
        #pragma unroll
        for (int kk = 0; kk < BK; kk++) {
            float4 a4 = *(const float4*)&As[cur][kk][ty * 4];
            float4 b4 = *(const float4*)&Bs[cur][kk][tx * 4];
            float a[4] = {a4.x, a4.y, a4.z, a4.w};
            float b[4] = {b4.x, b4.y, b4.z, b4.w};
            #pragma unroll
            for (int ii = 0; ii < 4; ii++)
                #pragma unroll
                for (int jj = 0; jj < 4; jj++)
                    acc[ii][jj] += a[ii] * b[jj];
        }
        if (it + 1 < NIT) {
            As[nxt][lcol + 0][lrow] = a_n.x; As[nxt][lcol + 1][lrow] = a_n.y;
            As[nxt][lcol + 2][lrow] = a_n.z; As[nxt][lcol + 3][lrow] = a_n.w;
            *(float4*)&Bs[nxt][br][bc] = b_n;
            __syncthreads();
        }
    }

    float* outp = g_yp[blockIdx.z];
    #pragma unroll
    for (int ii = 0; ii < 4; ii++) {
        int r = m0 + ty * 4 + ii;
        #pragma unroll
        for (int jj = 0; jj < 4; jj++)
            outp[(size_t)r * DM + n0 + tx * 4 + jj] = acc[ii][jj];
    }
}

// ---------------------------------------------------------------------------
// Kernel 5: ctx rows for one (h,b): ctx[b][h*64+d] = Wv_h[d] . y + bv.
// grid (NH, B_), 256 threads; warp w handles 8 rows, dual-row ILP.
// ---------------------------------------------------------------------------
__global__ void ctx_kernel(const float* __restrict__ Wv,
                           const float* __restrict__ bv) {
    int h = blockIdx.x, b = blockIdx.y;
    __shared__ float ys[DM];
    int tid = threadIdx.x;           // 256
    int w = tid >> 5, lane = tid & 31;

    if (tid < 128) {
        float4 v = make_float4(0.f, 0.f, 0.f, 0.f);
        size_t off = (size_t)(h * B_ + b) * DM;
        #pragma unroll
        for (int z = 0; z < YSPLIT; z++) {
            float4 p = ((const float4*)(g_yp[z] + off))[tid];
            v.x += p.x; v.y += p.y; v.z += p.z; v.w += p.w;
        }
        ((float4*)ys)[tid] = v;
    }
    __syncthreads();

    #pragma unroll
    for (int jj = 0; jj < 8; jj += 2) {
        int j0 = h * DH + w * 8 + jj;
        const float* w0 = Wv + (size_t)j0 * DM;
        const float* w1 = w0 + DM;
        float s0 = 0.f, s1 = 0.f;
        #pragma unroll
        for (int e0 = lane * 4; e0 < DM; e0 += 128) {
            float4 y4 = *(const float4*)(ys + e0);
            float4 a0 = *(const float4*)(w0 + e0);
            float4 a1 = *(const float4*)(w1 + e0);
            s0 += a0.x * y4.x + a0.y * y4.y + a0.z * y4.z + a0.w * y4.w;
            s1 += a1.x * y4.x + a1.y * y4.y + a1.z * y4.z + a1.w * y4.w;
        }
        #pragma unroll
        for (int off = 16; off; off >>= 1) {
            s0 += __shfl_xor_sync(0xffffffffu, s0, off);
            s1 += __shfl_xor_sync(0xffffffffu, s1, off);
        }
        if (lane == 0) {
            g_ctx[b * DM + j0]     = s0 + bv[j0];
            g_ctx[b * DM + j0 + 1] = s1 + bv[j0 + 1];
        }
    }
}

// ---------------------------------------------------------------------------
// Kernel 6: MLP head per batch. 32 blocks, 256 threads, dual-row dots.
// ---------------------------------------------------------------------------
__global__ void mlp_kernel(const float* __restrict__ W1,
                           const float* __restrict__ b1,
                           const float* __restrict__ W2,
                           const float* __restrict__ b2,
                           float* __restrict__ out) {
    int b = blockIdx.x;
    __shared__ float cs[DM];
    __shared__ float hs[DM];
    __shared__ float o8[8];
    int tid = threadIdx.x;           // 256
    int w = tid >> 5, lane = tid & 31;

    for (int e = tid; e < DM; e += 256) cs[e] = g_ctx[b * DM + e];
    __syncthreads();

    // layer 1: warp w handles rows [w*64, w*64+64), dual-row
    for (int jj = 0; jj < DH; jj += 2) {
        int j0 = w * DH + jj;
        const float* w0 = W1 + (size_t)j0 * DM;
        const float* w1 = w0 + DM;
        float s0 = 0.f, s1 = 0.f;
        #pragma unroll
        for (int e0 = lane * 4; e0 < DM; e0 += 128) {
            float4 c4 = *(const float4*)(cs + e0);
            float4 a0 = *(const float4*)(w0 + e0);
            float4 a1 = *(const float4*)(w1 + e0);
            s0 += a0.x * c4.x + a0.y * c4.y + a0.z * c4.z + a0.w * c4.w;
            s1 += a1.x * c4.x + a1.y * c4.y + a1.z * c4.z + a1.w * c4.w;
        }
        #pragma unroll
        for (int off = 16; off; off >>= 1) {
            s0 += __shfl_xor_sync(0xffffffffu, s0, off);
            s1 += __shfl_xor_sync(0xffffffffu, s1, off);
        }
        if (lane == 0) {
            float v0 = s0 + b1[j0];
            float v1 = s1 + b1[j0 + 1];
            hs[j0]     = (v0 > 0.f) ? v0 : 0.01f * v0;
            hs[j0 + 1] = (v1 > 0.f) ? v1 : 0.01f * v1;
        }
    }
    __syncthreads();

    // layer 2: warp w -> output row w
    {
        const float* wr = W2 + (size_t)w * DM;
        float s = 0.f;
        #pragma unroll
        for (int e0 = lane * 4; e0 < DM; e0 += 128) {
            float4 a = *(const float4*)(wr + e0);
            float4 h4 = *(const float4*)(hs + e0);
            s += a.x * h4.x + a.y * h4.y + a.z * h4.z + a.w * h4.w;
        }
        #pragma unroll
        for (int off = 16; off; off >>= 1) s += __shfl_xor_sync(0xffffffffu, s, off);
        if (lane == 0) {
            float v = s + b2[w];
            o8[w] = (v > 0.f) ? v : 0.f;
        }
    }
    __syncthreads();
    if (tid == 0) {
        float mv = 0.f;
        #pragma unroll
        for (int k = 0; k < 8; k++) mv += o8[k];
        mv *= 0.125f;
        out[b] = (mv > 0.f) ? mv : 0.01f * mv;
    }
}

// ---------------------------------------------------------------------------
extern "C" void kernel_launch(void* const* d_in, const int* in_sizes, int n_in,
                              void* d_out, int out_size) {
    const int* data    = (const int*)d_in[0];    // int32 (JAX x64 disabled)
    const int* lengths = (const int*)d_in[1];
    const float* emb = (const float*)d_in[2];
    const float* Wq  = (const float*)d_in[3];
    const float* bq  = (const float*)d_in[4];
    const float* Wk  = (const float*)d_in[5];
    // d_in[6] = bk: drops out of softmax (constant shift per row)
    const float* Wv  = (const float*)d_in[7];
    const float* bv  = (const float*)d_in[8];
    const float* W1  = (const float*)d_in[9];
    const float* b1  = (const float*)d_in[10];
    const float* W2  = (const float*)d_in[11];
    const float* b2  = (const float*)d_in[12];
    float* out = (float*)d_out;

    setup_kernel<<<XPAD + NI, 256>>>(data, lengths, emb, Wq, bq, Wk);
    d_gemm_kernel<<<dim3(XPAD / BN, NI / BM, DSPLIT), 256>>>();
    softmax_bin_kernel<<<dim3(NH, B_), 256>>>(data, lengths);
    y_gemm_kernel<<<dim3(DM / BN, NI / BM, YSPLIT), 256>>>();
    ctx_kernel<<<dim3(NH, B_), 256>>>(Wv, bv);
    mlp_kernel<<<B_, 256>>>(W1, b1, W2, b2, out);
}